// round 3
// baseline (speedup 1.0000x reference)
#include <cuda_runtime.h>
#include <math.h>

#define BATCH 4096
#define NIN   512
#define NREP  512
#define NOUT  640
#define RW    512
#define RB    64
#define NNZ   16384

// Scratch (static device globals — allowed)
__device__ float g_t[RW];
__device__ float g_Wp[NOUT * NIN];
__device__ float g_bp[NOUT];
__device__ float g_lin[BATCH * NOUT];
__device__ unsigned int g_si[NNZ];   // sorted-by-row: src | col<<10
__device__ float        g_sv[NNZ];   // sorted-by-row: bi_params
__device__ int          g_row_start[NOUT + 1];

// ---------------------------------------------------------------------------
// K0: zero the 512-float reduction target
// ---------------------------------------------------------------------------
__global__ void k_zero_t() {
    g_t[threadIdx.x] = 0.0f;
}

// ---------------------------------------------------------------------------
// Ksort: counting-sort the bilinear nnz by output row (CSR build).
// One block, 640 threads. Removes all atomics from the hot k4 kernel.
// ---------------------------------------------------------------------------
__global__ __launch_bounds__(640) void k_sort(const int* __restrict__ src,
                                              const int* __restrict__ row,
                                              const int* __restrict__ col,
                                              const float* __restrict__ p) {
    __shared__ int c[NOUT];
    __shared__ int start[NOUT + 1];
    __shared__ int off[NOUT];
    const int tid = threadIdx.x;
    c[tid] = 0;
    __syncthreads();
    for (int k = tid; k < NNZ; k += 640) atomicAdd(&c[row[k]], 1);
    __syncthreads();
    if (tid == 0) {
        int s = 0;
        for (int i = 0; i < NOUT; i++) { start[i] = s; s += c[i]; }
        start[NOUT] = s;
    }
    __syncthreads();
    off[tid] = start[tid];
    g_row_start[tid] = start[tid];
    if (tid == 0) g_row_start[NOUT] = start[NOUT];
    __syncthreads();
    for (int k = tid; k < NNZ; k += 640) {
        const int r = row[k];
        const int pos = atomicAdd(&off[r], 1);
        g_si[pos] = (unsigned)src[k] | ((unsigned)col[k] << 10);
        g_sv[pos] = p[k];
    }
}

// ---------------------------------------------------------------------------
// K1: t = Qw^T @ wflat      (streams Qw once — at DRAM roofline, keep)
// ---------------------------------------------------------------------------
__global__ __launch_bounds__(512) void k1_qwt(const float* __restrict__ Qw,
                                              const float* __restrict__ w) {
    __shared__ float s_w[256];
    const int tid = threadIdx.x;
    const int rowBase = blockIdx.x * 256;
    if (tid < 256) s_w[tid] = w[rowBase + tid];
    __syncthreads();

    float acc = 0.0f;
    const float* p = Qw + (size_t)rowBase * RW + tid;
#pragma unroll 8
    for (int i = 0; i < 256; i++) {
        acc += p[(size_t)i * RW] * s_w[i];
    }
    atomicAdd(&g_t[tid], acc);
}

// ---------------------------------------------------------------------------
// K1b: bp = Qb @ (Qb^T @ b)   (tiny)
// ---------------------------------------------------------------------------
__global__ __launch_bounds__(640) void k_bias(const float* __restrict__ Qb,
                                              const float* __restrict__ b) {
    __shared__ float s_s[RB];
    const int tid = threadIdx.x;
    if (tid < RB) {
        float acc = 0.0f;
        for (int i = 0; i < NOUT; i++) acc += Qb[i * RB + tid] * b[i];
        s_s[tid] = acc;
    }
    __syncthreads();
    if (tid < NOUT) {
        float acc = 0.0f;
#pragma unroll
        for (int r = 0; r < RB; r++) acc += Qb[tid * RB + r] * s_s[r];
        g_bp[tid] = acc;
    }
}

// ---------------------------------------------------------------------------
// K2: Wp[i] = dot(Qw[i,:], t)   (second Qw stream — at roofline, keep)
// ---------------------------------------------------------------------------
__global__ __launch_bounds__(256) void k2_wp(const float* __restrict__ Qw) {
    __shared__ float s_t[RW];
    const int tid = threadIdx.x;
    for (int i = tid; i < RW; i += 256) s_t[i] = g_t[i];
    __syncthreads();

    const int warp = tid >> 5;
    const int lane = tid & 31;
    const int row0 = (blockIdx.x * 8 + warp) * 16;
    const float4* t4 = reinterpret_cast<const float4*>(s_t);

    for (int rr = 0; rr < 16; rr++) {
        const int row = row0 + rr;
        const float4* p4 = reinterpret_cast<const float4*>(Qw + (size_t)row * RW);
        float acc = 0.0f;
#pragma unroll
        for (int u = 0; u < 4; u++) {
            float4 q = p4[lane + 32 * u];
            float4 tt = t4[lane + 32 * u];
            acc += q.x * tt.x + q.y * tt.y + q.z * tt.z + q.w * tt.w;
        }
#pragma unroll
        for (int off = 16; off > 0; off >>= 1)
            acc += __shfl_xor_sync(0xffffffffu, acc, off);
        if (lane == 0) g_Wp[row] = acc;
    }
}

// ---------------------------------------------------------------------------
// K3: lin = x @ Wp^T + bp   (4096x512 @ 512x640), f32x2-packed FMA GEMM
// ---------------------------------------------------------------------------
__global__ __launch_bounds__(256, 2) void k3_gemm(const float* __restrict__ x) {
    __shared__ float As[16][128];
    __shared__ float Bs[16][128];

    const int tid = threadIdx.x;
    const int tx = tid & 15;
    const int ty = tid >> 4;
    const int bn0 = blockIdx.x * 128;
    const int bm0 = blockIdx.y * 128;

    unsigned long long acc[8][4];
#pragma unroll
    for (int i = 0; i < 8; i++)
#pragma unroll
        for (int j = 0; j < 4; j++) acc[i][j] = 0ull;

    for (int k0 = 0; k0 < NIN; k0 += 16) {
#pragma unroll
        for (int i = 0; i < 2; i++) {
            const int idx = tid * 2 + i;
            const int m = idx >> 2;
            const int f4 = idx & 3;
            float4 v = *reinterpret_cast<const float4*>(
                x + (size_t)(bm0 + m) * NIN + k0 + f4 * 4);
            As[f4 * 4 + 0][m] = v.x;
            As[f4 * 4 + 1][m] = v.y;
            As[f4 * 4 + 2][m] = v.z;
            As[f4 * 4 + 3][m] = v.w;
        }
#pragma unroll
        for (int i = 0; i < 2; i++) {
            const int idx = tid * 2 + i;
            const int n = idx >> 2;
            const int f4 = idx & 3;
            float4 v = *reinterpret_cast<const float4*>(
                g_Wp + (size_t)(bn0 + n) * NIN + k0 + f4 * 4);
            Bs[f4 * 4 + 0][n] = v.x;
            Bs[f4 * 4 + 1][n] = v.y;
            Bs[f4 * 4 + 2][n] = v.z;
            Bs[f4 * 4 + 3][n] = v.w;
        }
        __syncthreads();

#pragma unroll
        for (int kk = 0; kk < 16; kk++) {
            unsigned long long a2[8];
#pragma unroll
            for (int i = 0; i < 8; i++) {
                float a = As[kk][ty * 8 + i];
                asm("mov.b64 %0, {%1, %1};" : "=l"(a2[i]) : "f"(a));
            }
            const unsigned long long* b2 =
                reinterpret_cast<const unsigned long long*>(&Bs[kk][tx * 8]);
            unsigned long long bb[4];
#pragma unroll
            for (int j = 0; j < 4; j++) bb[j] = b2[j];
#pragma unroll
            for (int i = 0; i < 8; i++)
#pragma unroll
                for (int j = 0; j < 4; j++)
                    asm("fma.rn.f32x2 %0, %1, %2, %0;"
                        : "+l"(acc[i][j]) : "l"(a2[i]), "l"(bb[j]));
        }
        __syncthreads();
    }

#pragma unroll
    for (int j = 0; j < 4; j++) {
        const int col = bn0 + tx * 8 + j * 2;
        const float bp0 = g_bp[col];
        const float bp1 = g_bp[col + 1];
#pragma unroll
        for (int i = 0; i < 8; i++) {
            float lo, hi;
            asm("mov.b64 {%0, %1}, %2;" : "=f"(lo), "=f"(hi) : "l"(acc[i][j]));
            const int row = bm0 + ty * 8 + i;
            float2 v = make_float2(lo + bp0, hi + bp1);
            *reinterpret_cast<float2*>(g_lin + (size_t)row * NOUT + col) = v;
        }
    }
}

// ---------------------------------------------------------------------------
// K4: bilinear (CSR, atomic-free) + preact + gated nonlinearity.
// Block = 256 threads = 8 warps; lanes = 32 batch elements; warps own rows.
// s_lin / s_pre: [channel][batch_lane], width padded to 33 (conflict-free for
// both lane-major gathers and channel-major epilogue reads).
// Dynamic smem: 2 * 640 * 33 * 4 = 168,960 B  -> one block per SM, 128 blocks.
// ---------------------------------------------------------------------------
#define K4_W 33
extern __shared__ float k4_smem[];

__global__ __launch_bounds__(256) void k4_bilinear_gate(
    const int* __restrict__ gate_idx, float* __restrict__ out) {
    float* s_lin = k4_smem;                 // [640][33]
    float* s_pre = k4_smem + NOUT * K4_W;   // [640][33]

    const int tid  = threadIdx.x;
    const int warp = tid >> 5;
    const int lane = tid & 31;
    const int b0   = blockIdx.x * 32;

    // Load 32 batch rows of lin: warp w loads rows w, w+8, w+16, w+24
#pragma unroll
    for (int i = 0; i < 4; i++) {
        const int bb = warp + 8 * i;
        const float* src = g_lin + (size_t)(b0 + bb) * NOUT;
#pragma unroll
        for (int ch = lane; ch < NOUT; ch += 32)
            s_lin[ch * K4_W + bb] = src[ch];
    }
    __syncthreads();

    // CSR bilinear: warp w handles rows w, w+8, ... ; lane = batch element.
    for (int row = warp; row < NOUT; row += 8) {
        const int ks = g_row_start[row];
        const int ke = g_row_start[row + 1];
        float acc = 0.0f;
        int k = ks;
        for (; k + 3 < ke; k += 4) {
#pragma unroll
            for (int u = 0; u < 4; u++) {
                const unsigned si = g_si[k + u];
                const float    sv = g_sv[k + u];
                acc += sv * s_lin[(si & 1023) * K4_W + lane] *
                            s_lin[((si >> 10) & 1023) * K4_W + lane];
            }
        }
        for (; k < ke; k++) {
            const unsigned si = g_si[k];
            acc += g_sv[k] * s_lin[(si & 1023) * K4_W + lane] *
                             s_lin[((si >> 10) & 1023) * K4_W + lane];
        }
        s_pre[row * K4_W + lane] = 0.1f * acc + s_lin[row * K4_W + lane];
    }
    __syncthreads();

    // Gated epilogue, remapped for coalesced stores:
    // warp w writes batch rows b0+w+8i; lanes sweep output channels.
#pragma unroll
    for (int i = 0; i < 4; i++) {
        const int bb = warp + 8 * i;
        float* dst = out + (size_t)(b0 + bb) * NREP;
        for (int j = lane; j < NREP; j += 32) {
            const int gi = gate_idx[j];
            const float g = s_pre[gi * K4_W + bb];
            const float sg = 1.0f / (1.0f + __expf(-g));
            dst[j] = sg * s_pre[j * K4_W + bb];
        }
    }
}

// ---------------------------------------------------------------------------
// Launch
// ---------------------------------------------------------------------------
extern "C" void kernel_launch(void* const* d_in, const int* in_sizes, int n_in,
                              void* d_out, int out_size) {
    const float* x        = (const float*)d_in[0];
    const float* W_weight = (const float*)d_in[1];
    const float* b        = (const float*)d_in[2];
    const float* Qw       = (const float*)d_in[3];
    const float* Qb       = (const float*)d_in[4];
    const float* bi_p     = (const float*)d_in[5];
    const int*   bi_src   = (const int*)d_in[6];
    const int*   bi_row   = (const int*)d_in[7];
    const int*   bi_col   = (const int*)d_in[8];
    const int*   gate_idx = (const int*)d_in[9];
    float* out = (float*)d_out;

    static int smem_set = 0;
    const int k4_smem_bytes = 2 * NOUT * K4_W * sizeof(float);
    if (!smem_set) {
        cudaFuncSetAttribute(k4_bilinear_gate,
                             cudaFuncAttributeMaxDynamicSharedMemorySize,
                             k4_smem_bytes);
        smem_set = 1;
    }

    k_zero_t<<<1, 512>>>();
    k_sort<<<1, 640>>>(bi_src, bi_row, bi_col, bi_p);
    k1_qwt<<<1280, 512>>>(Qw, W_weight);
    k_bias<<<1, 640>>>(Qb, b);
    k2_wp<<<2560, 256>>>(Qw);
    k3_gemm<<<dim3(NOUT / 128, BATCH / 128), 256>>>(x);
    k4_bilinear_gate<<<BATCH / 32, 256, k4_smem_bytes>>>(gate_idx, out);
}

// round 4
// speedup vs baseline: 1.1615x; 1.1615x over previous
#include <cuda_runtime.h>
#include <math.h>

#define BATCH 4096
#define NIN   512
#define NREP  512
#define NOUT  640
#define RW    512
#define RB    64
#define NNZ   16384

// Scratch (static device globals — allowed)
__device__ float g_t[RW];
__device__ float g_Wp[NOUT * NIN];
__device__ float g_bp[NOUT];
__device__ float g_lin[BATCH * NOUT];
__device__ unsigned int g_si[NNZ];   // sorted-by-row: src | col<<10
__device__ float        g_sv[NNZ];   // sorted-by-row: bi_params
__device__ int          g_row_start[NOUT + 1];

// ---------------------------------------------------------------------------
// Ksort: counting-sort bilinear nnz by output row (CSR build) + zero g_t.
// One block, 640 threads, parallel Hillis-Steele scan.
// ---------------------------------------------------------------------------
__global__ __launch_bounds__(640) void k_sort(const int* __restrict__ src,
                                              const int* __restrict__ row,
                                              const int* __restrict__ col,
                                              const float* __restrict__ p) {
    __shared__ int c[NOUT];
    __shared__ int scan[NOUT];
    __shared__ int off[NOUT];
    const int tid = threadIdx.x;
    if (tid < RW) g_t[tid] = 0.0f;   // zero reduction target for k1
    c[tid] = 0;
    __syncthreads();
    for (int k = tid; k < NNZ; k += 640) atomicAdd(&c[row[k]], 1);
    __syncthreads();
    scan[tid] = c[tid];
    __syncthreads();
#pragma unroll
    for (int d = 1; d < NOUT; d <<= 1) {
        int v = (tid >= d) ? scan[tid - d] : 0;
        __syncthreads();
        scan[tid] += v;
        __syncthreads();
    }
    const int start = scan[tid] - c[tid];   // exclusive
    g_row_start[tid] = start;
    if (tid == NOUT - 1) g_row_start[NOUT] = scan[tid];
    off[tid] = start;
    __syncthreads();
    for (int k = tid; k < NNZ; k += 640) {
        const int r = row[k];
        const int pos = atomicAdd(&off[r], 1);
        g_si[pos] = (unsigned)src[k] | ((unsigned)col[k] << 10);
        g_sv[pos] = p[k];
    }
}

// ---------------------------------------------------------------------------
// K1: t = Qw^T @ wflat   (streams Qw once — measured at DRAM roofline, keep)
// ---------------------------------------------------------------------------
__global__ __launch_bounds__(512) void k1_qwt(const float* __restrict__ Qw,
                                              const float* __restrict__ w) {
    __shared__ float s_w[256];
    const int tid = threadIdx.x;
    const int rowBase = blockIdx.x * 256;
    if (tid < 256) s_w[tid] = w[rowBase + tid];
    __syncthreads();

    float acc = 0.0f;
    const float* p = Qw + (size_t)rowBase * RW + tid;
#pragma unroll 8
    for (int i = 0; i < 256; i++) {
        acc += p[(size_t)i * RW] * s_w[i];
    }
    atomicAdd(&g_t[tid], acc);
}

// ---------------------------------------------------------------------------
// K1b: bp = Qb @ (Qb^T @ b)   — parallel rewrite (was 64.6us serial-latency)
// Phase 1: 512 threads = (64 r) x (8 chunks of 80 i) coalesced partials.
// Phase 2: 640 threads, each a float4-vectorized 64-dot.
// ---------------------------------------------------------------------------
__global__ __launch_bounds__(640) void k_bias(const float* __restrict__ Qb,
                                              const float* __restrict__ b) {
    __shared__ float s_part[8][RB];
    __shared__ float s_s[RB];
    const int tid = threadIdx.x;

    if (tid < 512) {
        const int r = tid & 63;
        const int chunk = tid >> 6;
        float acc = 0.0f;
#pragma unroll 10
        for (int i = chunk * 80; i < chunk * 80 + 80; i++)
            acc += Qb[i * RB + r] * b[i];
        s_part[chunk][r] = acc;
    }
    __syncthreads();
    if (tid < RB) {
        float acc = 0.0f;
#pragma unroll
        for (int ch = 0; ch < 8; ch++) acc += s_part[ch][tid];
        s_s[tid] = acc;
    }
    __syncthreads();
    {
        const float4* q4 = reinterpret_cast<const float4*>(Qb + tid * RB);
        const float4* s4 = reinterpret_cast<const float4*>(s_s);
        float acc = 0.0f;
#pragma unroll
        for (int u = 0; u < 16; u++) {
            float4 q = q4[u];
            float4 s = s4[u];
            acc += q.x * s.x + q.y * s.y + q.z * s.z + q.w * s.w;
        }
        g_bp[tid] = acc;
    }
}

// ---------------------------------------------------------------------------
// K2: Wp[i] = dot(Qw[i,:], t)   (second Qw stream — at roofline, keep)
// ---------------------------------------------------------------------------
__global__ __launch_bounds__(256) void k2_wp(const float* __restrict__ Qw) {
    __shared__ float s_t[RW];
    const int tid = threadIdx.x;
    for (int i = tid; i < RW; i += 256) s_t[i] = g_t[i];
    __syncthreads();

    const int warp = tid >> 5;
    const int lane = tid & 31;
    const int row0 = (blockIdx.x * 8 + warp) * 16;
    const float4* t4 = reinterpret_cast<const float4*>(s_t);

    for (int rr = 0; rr < 16; rr++) {
        const int row = row0 + rr;
        const float4* p4 = reinterpret_cast<const float4*>(Qw + (size_t)row * RW);
        float acc = 0.0f;
#pragma unroll
        for (int u = 0; u < 4; u++) {
            float4 q = p4[lane + 32 * u];
            float4 tt = t4[lane + 32 * u];
            acc += q.x * tt.x + q.y * tt.y + q.z * tt.z + q.w * tt.w;
        }
#pragma unroll
        for (int off = 16; off > 0; off >>= 1)
            acc += __shfl_xor_sync(0xffffffffu, acc, off);
        if (lane == 0) g_Wp[row] = acc;
    }
}

// ---------------------------------------------------------------------------
// K3: lin_nobias = x @ Wp^T   (4096x512 @ 512x640)
// 128x160 tile, 256 threads, 8x10 per-thread f32x2 tile.
// grid = (640/160, 4096/128) = (4, 32) = 128 blocks = exactly one wave.
// No launch_bounds occupancy cap -> no register spills (acc=80 regs).
// Bias is folded into K4's load instead.
// ---------------------------------------------------------------------------
#define BNK3 160
__global__ __launch_bounds__(256) void k3_gemm(const float* __restrict__ x) {
    __shared__ float As[16][128];
    __shared__ float Bs[16][BNK3];

    const int tid = threadIdx.x;
    const int tx = tid & 15;    // 16 -> 10 cols each
    const int ty = tid >> 4;    // 16 -> 8 rows each
    const int bn0 = blockIdx.x * BNK3;
    const int bm0 = blockIdx.y * 128;

    unsigned long long acc[8][5];
#pragma unroll
    for (int i = 0; i < 8; i++)
#pragma unroll
        for (int j = 0; j < 5; j++) acc[i][j] = 0ull;

    for (int k0 = 0; k0 < NIN; k0 += 16) {
        // A tile: 128 rows x 16 k = 512 float4, 2 per thread
#pragma unroll
        for (int i = 0; i < 2; i++) {
            const int idx = tid * 2 + i;
            const int m = idx >> 2;
            const int f4 = idx & 3;
            float4 v = *reinterpret_cast<const float4*>(
                x + (size_t)(bm0 + m) * NIN + k0 + f4 * 4);
            As[f4 * 4 + 0][m] = v.x;
            As[f4 * 4 + 1][m] = v.y;
            As[f4 * 4 + 2][m] = v.z;
            As[f4 * 4 + 3][m] = v.w;
        }
        // B tile: 160 n-rows x 16 k = 640 float4, 2.5 per thread
        for (int idx = tid; idx < 640; idx += 256) {
            const int n = idx >> 2;
            const int f4 = idx & 3;
            float4 v = *reinterpret_cast<const float4*>(
                g_Wp + (size_t)(bn0 + n) * NIN + k0 + f4 * 4);
            Bs[f4 * 4 + 0][n] = v.x;
            Bs[f4 * 4 + 1][n] = v.y;
            Bs[f4 * 4 + 2][n] = v.z;
            Bs[f4 * 4 + 3][n] = v.w;
        }
        __syncthreads();

#pragma unroll
        for (int kk = 0; kk < 16; kk++) {
            unsigned long long a2[8];
#pragma unroll
            for (int i = 0; i < 8; i++) {
                float a = As[kk][ty * 8 + i];
                asm("mov.b64 %0, {%1, %1};" : "=l"(a2[i]) : "f"(a));
            }
            const unsigned long long* b2 =
                reinterpret_cast<const unsigned long long*>(&Bs[kk][tx * 10]);
            unsigned long long bb[5];
#pragma unroll
            for (int j = 0; j < 5; j++) bb[j] = b2[j];
#pragma unroll
            for (int i = 0; i < 8; i++)
#pragma unroll
                for (int j = 0; j < 5; j++)
                    asm("fma.rn.f32x2 %0, %1, %2, %0;"
                        : "+l"(acc[i][j]) : "l"(a2[i]), "l"(bb[j]));
        }
        __syncthreads();
    }

#pragma unroll
    for (int i = 0; i < 8; i++) {
        const int row = bm0 + ty * 8 + i;
#pragma unroll
        for (int j = 0; j < 5; j++) {
            const int col = bn0 + tx * 10 + j * 2;
            float lo, hi;
            asm("mov.b64 {%0, %1}, %2;" : "=f"(lo), "=f"(hi) : "l"(acc[i][j]));
            *reinterpret_cast<float2*>(g_lin + (size_t)row * NOUT + col) =
                make_float2(lo, hi);
        }
    }
}

// ---------------------------------------------------------------------------
// K4: bias add + bilinear (CSR, atomic-free) + preact + gated nonlinearity.
// Block = 8 warps; lanes = 32 batch elements; warps own output rows.
// ---------------------------------------------------------------------------
#define K4_W 33
extern __shared__ float k4_smem[];

__global__ __launch_bounds__(256) void k4_bilinear_gate(
    const int* __restrict__ gate_idx, float* __restrict__ out) {
    float* s_lin = k4_smem;                 // [640][33]
    float* s_pre = k4_smem + NOUT * K4_W;   // [640][33]

    const int tid  = threadIdx.x;
    const int warp = tid >> 5;
    const int lane = tid & 31;
    const int b0   = blockIdx.x * 32;

    // Load 32 batch rows of lin, adding the equivariant bias here.
#pragma unroll
    for (int i = 0; i < 4; i++) {
        const int bb = warp + 8 * i;
        const float* src = g_lin + (size_t)(b0 + bb) * NOUT;
        for (int ch = lane; ch < NOUT; ch += 32)
            s_lin[ch * K4_W + bb] = src[ch] + g_bp[ch];
    }
    __syncthreads();

    // CSR bilinear: warp w handles rows w, w+8, ...; lane = batch element.
    for (int row = warp; row < NOUT; row += 8) {
        const int ks = g_row_start[row];
        const int ke = g_row_start[row + 1];
        float acc = 0.0f;
        int k = ks;
        for (; k + 3 < ke; k += 4) {
#pragma unroll
            for (int u = 0; u < 4; u++) {
                const unsigned si = g_si[k + u];
                const float    sv = g_sv[k + u];
                acc += sv * s_lin[(si & 1023) * K4_W + lane] *
                            s_lin[((si >> 10) & 1023) * K4_W + lane];
            }
        }
        for (; k < ke; k++) {
            const unsigned si = g_si[k];
            acc += g_sv[k] * s_lin[(si & 1023) * K4_W + lane] *
                             s_lin[((si >> 10) & 1023) * K4_W + lane];
        }
        s_pre[row * K4_W + lane] = 0.1f * acc + s_lin[row * K4_W + lane];
    }
    __syncthreads();

    // Gated epilogue, coalesced stores.
#pragma unroll
    for (int i = 0; i < 4; i++) {
        const int bb = warp + 8 * i;
        float* dst = out + (size_t)(b0 + bb) * NREP;
        for (int j = lane; j < NREP; j += 32) {
            const int gi = gate_idx[j];
            const float g = s_pre[gi * K4_W + bb];
            const float sg = 1.0f / (1.0f + __expf(-g));
            dst[j] = sg * s_pre[j * K4_W + bb];
        }
    }
}

// ---------------------------------------------------------------------------
// Launch  (k3 is launch #4 so ncu -s5 profiles it next round)
// ---------------------------------------------------------------------------
extern "C" void kernel_launch(void* const* d_in, const int* in_sizes, int n_in,
                              void* d_out, int out_size) {
    const float* x        = (const float*)d_in[0];
    const float* W_weight = (const float*)d_in[1];
    const float* b        = (const float*)d_in[2];
    const float* Qw       = (const float*)d_in[3];
    const float* Qb       = (const float*)d_in[4];
    const float* bi_p     = (const float*)d_in[5];
    const int*   bi_src   = (const int*)d_in[6];
    const int*   bi_row   = (const int*)d_in[7];
    const int*   bi_col   = (const int*)d_in[8];
    const int*   gate_idx = (const int*)d_in[9];
    float* out = (float*)d_out;

    static int smem_set = 0;
    const int k4_smem_bytes = 2 * NOUT * K4_W * sizeof(float);
    if (!smem_set) {
        cudaFuncSetAttribute(k4_bilinear_gate,
                             cudaFuncAttributeMaxDynamicSharedMemorySize,
                             k4_smem_bytes);
        smem_set = 1;
    }

    k_sort<<<1, 640>>>(bi_src, bi_row, bi_col, bi_p);   // also zeros g_t
    k1_qwt<<<1280, 512>>>(Qw, W_weight);
    k2_wp<<<2560, 256>>>(Qw);
    k3_gemm<<<dim3(NOUT / BNK3, BATCH / 128), 256>>>(x);
    k_bias<<<1, 640>>>(Qb, b);
    k4_bilinear_gate<<<BATCH / 32, 256, k4_smem_bytes>>>(gate_idx, out);
}